// round 11
// baseline (speedup 1.0000x reference)
#include <cuda_runtime.h>
#include <math.h>

// ---------------------------------------------------------------------------
// S2ConvNetModified pipeline, fp32 SIMT implementation.
// Stages:
//  A: c[32,121]        = xT[32,9216] @ from_s2^T
//  B: psi1[20,121]     = (Yk1^T @ w1) / sqrt(24)
//  C: h1[640,1771]     = per-l outer products of c and psi1
//  D: G[640,32000]     = ACT * relu(h1 @ D1_to^T)           (GEMM, MODE 0)
//  E: h2[640,286]      = G @ F1_from^T                       (split-K GEMM, MODE 1)
//  F: psi2[800,286]    = (Dk2^T @ w2) / sqrt(168)
//  G: h3[1280,286]     = block-diag Wigner conv2 (smem-cached)
//  H: out[1280]        = sum_g F2_from[g]*ACT*relu(h3 @ D2_to^T)  (fused GEMM, MODE 2)
// ---------------------------------------------------------------------------

#define ACT_CST 1.4142135623730951f

// scratch (device globals: no runtime allocation allowed)
__device__ float g_c[32 * 121];
__device__ float g_psi1[20 * 121];
__device__ float g_h1[640 * 1771];
__device__ float g_G[640 * 32000];     // 82 MB grid activations
__device__ float g_h2[640 * 286];
__device__ float g_psi2[800 * 286];
__device__ float g_h3[1280 * 286];

// cumulative sum of (2l+1)^2, l = 0..10  (FIXED: previous table wrong for l>=6)
__constant__ int OFF1c[12] = {0, 1, 10, 35, 84, 165, 286, 455, 680, 969, 1330, 1771};
__constant__ int OFF2c[7]  = {0, 1, 10, 35, 84, 165, 286};

// --------------------------- stage A: from_s2 ------------------------------
// c[b,m] = sum_{beta,alpha} x[b,0,alpha,beta] * from_s2[m, beta*96+alpha]
__global__ void k_from_s2(const float* __restrict__ x, const float* __restrict__ from_s2) {
    int m = blockIdx.x;   // 0..120
    int b = blockIdx.y;   // 0..31
    int t = threadIdx.x;  // 128 threads
    const float* fr = from_s2 + (size_t)m * 9216;
    const float* xb = x + (size_t)b * 9216;
    float acc = 0.f;
    for (int idx = t; idx < 9216; idx += 128) {
        int be = idx / 96;
        int a  = idx - be * 96;
        acc += fr[idx] * xb[a * 96 + be];
    }
    __shared__ float red[128];
    red[t] = acc;
    __syncthreads();
    for (int s = 64; s > 0; s >>= 1) {
        if (t < s) red[t] += red[t + s];
        __syncthreads();
    }
    if (t == 0) g_c[b * 121 + m] = red[0];
}

// --------------------------- stage B: psi1 ---------------------------------
__global__ void k_psi1(const float* __restrict__ Yk1, const float* __restrict__ w1) {
    int j = blockIdx.x;       // 0..19
    int m = threadIdx.x;      // 128 threads, guard 121
    if (m < 121) {
        float acc = 0.f;
        for (int p = 0; p < 24; p++)
            acc += Yk1[p * 121 + m] * w1[j * 24 + p];
        g_psi1[j * 121 + m] = acc * 0.20412414523193154f;  // 1/sqrt(24)
    }
}

// --------------------------- stage C: h1 -----------------------------------
// h1[b,j, OFF1[l] + n*k + m] = c[b, l*l + m] * psi1[j, l*l + n]
__global__ void k_h1() {
    int bj = blockIdx.x;      // 0..639 = b*20+j
    int b = bj / 20, j = bj - b * 20;
    const float* cb = g_c + b * 121;
    const float* pj = g_psi1 + j * 121;
    float* out = g_h1 + (size_t)bj * 1771;
    for (int cidx = threadIdx.x; cidx < 1771; cidx += blockDim.x) {
        int l = 0;
        while (OFF1c[l + 1] <= cidx) l++;
        int k = 2 * l + 1;
        int local = cidx - OFF1c[l];
        int n = local / k;
        int m = local - n * k;
        out[cidx] = cb[l * l + m] * pj[l * l + n];
    }
}

// --------------------------- stage F: psi2 ---------------------------------
__global__ void k_psi2(const float* __restrict__ Dk2, const float* __restrict__ w2) {
    int ij = blockIdx.x;      // 0..799 = i*40+j
    int c = threadIdx.x;      // 320 threads, guard 286
    if (c < 286) {
        const float* w = w2 + ij * 168;
        float acc = 0.f;
        for (int n = 0; n < 168; n++)
            acc += Dk2[n * 286 + c] * w[n];
        g_psi2[ij * 286 + c] = acc * 0.07715167498104596f;  // 1/sqrt(168)
    }
}

// --------------------------- zero init -------------------------------------
__global__ void k_zero(float* __restrict__ out) {
    int i = blockIdx.x * blockDim.x + threadIdx.x;
    if (i < 640 * 286) g_h2[i] = 0.f;
    if (i < 1280) out[i] = 0.f;
}

// --------------------------- tiled NT GEMM ---------------------------------
// C[M,N] = A[M,K] * B[N,K]^T ; BM=128, BN=64, BK=16, 256 threads, 8x4 microtile
// MODE 0: A=g_h1, C=g_G, relu*ACT epilogue            (M=640,  N=32000, K=1771)
// MODE 1: A=g_G,  C=g_h2, split-K atomic epilogue     (M=640,  N=286,   K=32000, klen=800)
// MODE 2: A=g_h3, fused relu*ACT*wvec reduce -> Cout  (M=1280, N=6912,  K=286)
template <int MODE>
__global__ void __launch_bounds__(256)
gemm_nt(const float* __restrict__ B, float* __restrict__ Cout,
        const float* __restrict__ wvec) {
    constexpr int M    = (MODE == 0) ? 640   : (MODE == 1) ? 640   : 1280;
    constexpr int N    = (MODE == 0) ? 32000 : (MODE == 1) ? 286   : 6912;
    constexpr int K    = (MODE == 0) ? 1771  : (MODE == 1) ? 32000 : 286;
    constexpr int KLEN = (MODE == 1) ? 800 : K;
    (void)M;

    const float* A = (MODE == 0) ? g_h1 : (MODE == 1) ? g_G : g_h3;
    float* C       = (MODE == 0) ? g_G  : (MODE == 1) ? g_h2 : Cout;

    __shared__ __align__(16) float As[16][132];  // pad 4: stride 528B (16B mult)
    __shared__ __align__(16) float Bs[16][68];   // pad 4: stride 272B (16B mult)

    const int t  = threadIdx.x;
    const int tx = t & 15;
    const int ty = t >> 4;
    const int m0 = blockIdx.y * 128;
    const int n0 = blockIdx.x * 64;
    const int kstart = (MODE == 1) ? (int)blockIdx.z * KLEN : 0;

    float acc[8][4];
#pragma unroll
    for (int i = 0; i < 8; i++)
#pragma unroll
        for (int j = 0; j < 4; j++) acc[i][j] = 0.f;

    const int kA = t & 15;   // k within tile (coalesced along K)
    const int rA = t >> 4;   // row/col base

    for (int kk = 0; kk < KLEN; kk += 16) {
        const bool kok = (kk + kA) < KLEN;
        const int kg = kstart + kk + kA;
#pragma unroll
        for (int i = 0; i < 8; i++) {
            int m = rA + 16 * i;
            As[kA][m] = kok ? A[(size_t)(m0 + m) * K + kg] : 0.f;
        }
#pragma unroll
        for (int i = 0; i < 4; i++) {
            int n = rA + 16 * i;
            Bs[kA][n] = (kok && (n0 + n) < N) ? B[(size_t)(n0 + n) * K + kg] : 0.f;
        }
        __syncthreads();
#pragma unroll
        for (int k = 0; k < 16; k++) {
            float4 a0 = *(const float4*)&As[k][ty * 8];
            float4 a1 = *(const float4*)&As[k][ty * 8 + 4];
            float4 bv = *(const float4*)&Bs[k][tx * 4];
            float av[8] = {a0.x, a0.y, a0.z, a0.w, a1.x, a1.y, a1.z, a1.w};
            float bb[4] = {bv.x, bv.y, bv.z, bv.w};
#pragma unroll
            for (int i = 0; i < 8; i++)
#pragma unroll
                for (int j = 0; j < 4; j++)
                    acc[i][j] = fmaf(av[i], bb[j], acc[i][j]);
        }
        __syncthreads();
    }

    if (MODE == 0) {
#pragma unroll
        for (int i = 0; i < 8; i++) {
            int row = m0 + ty * 8 + i;
            float4 v;
            v.x = fmaxf(acc[i][0], 0.f) * ACT_CST;
            v.y = fmaxf(acc[i][1], 0.f) * ACT_CST;
            v.z = fmaxf(acc[i][2], 0.f) * ACT_CST;
            v.w = fmaxf(acc[i][3], 0.f) * ACT_CST;
            *(float4*)&C[(size_t)row * N + n0 + tx * 4] = v;
        }
    } else if (MODE == 1) {
#pragma unroll
        for (int i = 0; i < 8; i++) {
            int row = m0 + ty * 8 + i;
#pragma unroll
            for (int j = 0; j < 4; j++) {
                int n = n0 + tx * 4 + j;
                if (n < N) atomicAdd(&C[row * N + n], acc[i][j]);
            }
        }
    } else {
#pragma unroll
        for (int i = 0; i < 8; i++) {
            int row = m0 + ty * 8 + i;
            float s = 0.f;
#pragma unroll
            for (int j = 0; j < 4; j++)
                s += fmaxf(acc[i][j], 0.f) * wvec[n0 + tx * 4 + j];
            atomicAdd(&C[row], s * ACT_CST);
        }
    }
}

// --------------------------- stage G: conv2 --------------------------------
// h3[b,j, off+v*k+m] = (1/sqrt(20k)) * sum_{i<20,u<k} h2[b,i,off+u*k+m]*psi2[i,j,off+u*k+v]
__global__ void __launch_bounds__(320) k_conv2() {
    int bj = blockIdx.x;      // 0..1279 = b*40+j
    int b = bj / 40, j = bj - b * 40;
    __shared__ float h2s[20 * 286];
    __shared__ float ps[20 * 286];
    for (int idx = threadIdx.x; idx < 20 * 286; idx += blockDim.x) {
        int i = idx / 286, c = idx - i * 286;
        h2s[idx] = g_h2[(b * 20 + i) * 286 + c];
        ps[idx]  = g_psi2[(i * 40 + j) * 286 + c];
    }
    __syncthreads();
    int c = threadIdx.x;
    if (c < 286) {
        int l = 0;
        while (OFF2c[l + 1] <= c) l++;
        int k = 2 * l + 1;
        int local = c - OFF2c[l];
        int v = local / k;
        int m = local - v * k;
        int off = OFF2c[l];
        float acc = 0.f;
        for (int i = 0; i < 20; i++) {
            const float* hr = h2s + i * 286 + off;
            const float* pr = ps + i * 286 + off;
            for (int u = 0; u < k; u++)
                acc = fmaf(hr[u * k + m], pr[u * k + v], acc);
        }
        g_h3[bj * 286 + c] = acc * (1.0f / sqrtf(20.0f * (float)k));
    }
}

// --------------------------- launcher --------------------------------------
extern "C" void kernel_launch(void* const* d_in, const int* in_sizes, int n_in,
                              void* d_out, int out_size) {
    const float* x       = (const float*)d_in[0];
    const float* w1      = (const float*)d_in[1];
    const float* w2      = (const float*)d_in[2];
    const float* Yk1     = (const float*)d_in[3];
    const float* Dk2     = (const float*)d_in[4];
    const float* from_s2 = (const float*)d_in[5];
    const float* D1_to   = (const float*)d_in[6];
    const float* F1_from = (const float*)d_in[7];
    const float* D2_to   = (const float*)d_in[8];
    const float* F2_from = (const float*)d_in[9];
    float* out = (float*)d_out;
    (void)in_sizes; (void)n_in; (void)out_size;

    // zero h2 (split-K accumulation) and out (atomic epilogue)
    k_zero<<<(640 * 286 + 255) / 256, 256>>>(out);

    // A: S2 analysis
    k_from_s2<<<dim3(121, 32), 128>>>(x, from_s2);
    // B: SH kernel weights
    k_psi1<<<20, 128>>>(Yk1, w1);
    // C: conv1 outer products
    k_h1<<<640, 256>>>();
    // D: big grid GEMM + relu  (dominant cost)
    gemm_nt<0><<<dim3(500, 5, 1), 256>>>(D1_to, nullptr, nullptr);
    // F: Wigner kernel weights
    k_psi2<<<800, 320>>>(Dk2, w2);
    // E: grid -> Fourier, split-K over K=32000 (40 chunks of 800)
    gemm_nt<1><<<dim3(5, 5, 40), 256>>>(F1_from, nullptr, nullptr);
    // G: SO(3) conv layer 2
    k_conv2<<<1280, 320>>>();
    // H: final activation + projection, fused reduce into out
    gemm_nt<2><<<dim3(108, 10, 1), 256>>>(D2_to, out, F2_from);
}

// round 13
// speedup vs baseline: 1.8412x; 1.8412x over previous
#include <cuda_runtime.h>
#include <cuda_bf16.h>
#include <math.h>
#include <stdint.h>

// ---------------------------------------------------------------------------
// S2ConvNetModified pipeline.
// GEMM1 (72.5 GF grid transform) on warp-level bf16 mma.sync (HMMA) with a
// 3-term bf16 error split (hh + hl + lh) for fp32-class precision.
// tcgen05 is NOT available (harness compiles PTX at plain sm_103 target).
// Everything else stays fp32 SIMT (proven passing in R11).
// ---------------------------------------------------------------------------

#define ACT_CST 1.4142135623730951f

// ----- scratch (device globals; no runtime allocation allowed) -------------
__device__ float g_c[32 * 121];
__device__ float g_psi1[20 * 121];
__device__ float g_xT[32 * 9216];
__device__ __align__(16) __nv_bfloat16 g_h1b[640 * 3584];            // [hi|lo], Kp=1792
__device__ __align__(16) __nv_bfloat16 g_Db[(size_t)32000 * 3584];   // [hi|lo] of D1_to
__device__ float g_G[(size_t)640 * 32000];
__device__ float g_h2[640 * 286];
__device__ float g_psi2[800 * 286];
__device__ float g_h3[1280 * 286];

__constant__ int OFF1c[12] = {0, 1, 10, 35, 84, 165, 286, 455, 680, 969, 1330, 1771};
__constant__ int OFF2c[7]  = {0, 1, 10, 35, 84, 165, 286};

// ----------------------------- helpers -------------------------------------
__device__ __forceinline__ uint32_t smem_u32(const void* p) {
    uint32_t a;
    asm("{ .reg .u64 t; cvta.to.shared.u64 t, %1; cvt.u32.u64 %0, t; }"
        : "=r"(a) : "l"(p));
    return a;
}
__device__ __forceinline__ void cp16(uint32_t dst, const void* src) {
    asm volatile("cp.async.cg.shared.global [%0], [%1], 16;" :: "r"(dst), "l"(src));
}
#define CP_COMMIT() asm volatile("cp.async.commit_group;" ::: "memory")
#define CP_WAIT1()  asm volatile("cp.async.wait_group 1;" ::: "memory")
#define CP_WAIT0()  asm volatile("cp.async.wait_group 0;" ::: "memory")

__device__ __forceinline__ void mma16816(float* c, const uint32_t* a, const uint32_t* b) {
    asm volatile(
        "mma.sync.aligned.m16n8k16.row.col.f32.bf16.bf16.f32 "
        "{%0,%1,%2,%3},{%4,%5,%6,%7},{%8,%9},{%0,%1,%2,%3};"
        : "+f"(c[0]), "+f"(c[1]), "+f"(c[2]), "+f"(c[3])
        : "r"(a[0]), "r"(a[1]), "r"(a[2]), "r"(a[3]), "r"(b[0]), "r"(b[1]));
}

// --------------------------- x transpose -----------------------------------
// g_xT[b][beta*96 + alpha] = x[b][alpha*96 + beta]
__global__ void k_xT(const float* __restrict__ x) {
    __shared__ float t[32][33];
    int b = blockIdx.y;
    int ta = (blockIdx.x % 3) * 32, tb = (blockIdx.x / 3) * 32;
    t[threadIdx.y][threadIdx.x] = x[b * 9216 + (ta + threadIdx.y) * 96 + tb + threadIdx.x];
    __syncthreads();
    g_xT[b * 9216 + (tb + threadIdx.y) * 96 + ta + threadIdx.x] = t[threadIdx.x][threadIdx.y];
}

// --------------------------- stage A: from_s2 ------------------------------
__global__ void k_from_s2(const float* __restrict__ from_s2) {
    int m = blockIdx.x, b = blockIdx.y, t = threadIdx.x;
    const float* fr = from_s2 + (size_t)m * 9216;
    const float* xb = g_xT + (size_t)b * 9216;
    float acc = 0.f;
    for (int idx = t; idx < 9216; idx += 128) acc += fr[idx] * xb[idx];
    __shared__ float red[128];
    red[t] = acc;
    __syncthreads();
    for (int s = 64; s > 0; s >>= 1) {
        if (t < s) red[t] += red[t + s];
        __syncthreads();
    }
    if (t == 0) g_c[b * 121 + m] = red[0];
}

// --------------------------- stage B: psi1 ---------------------------------
__global__ void k_psi1(const float* __restrict__ Yk1, const float* __restrict__ w1) {
    int j = blockIdx.x, m = threadIdx.x;
    if (m < 121) {
        float acc = 0.f;
        for (int p = 0; p < 24; p++) acc += Yk1[p * 121 + m] * w1[j * 24 + p];
        g_psi1[j * 121 + m] = acc * 0.20412414523193154f;
    }
}

// --------------------------- stage C: h1 (bf16 split) ----------------------
__global__ void k_h1b() {
    int bj = blockIdx.x;
    int b = bj / 20, j = bj - b * 20;
    const float* cb = g_c + b * 121;
    const float* pj = g_psi1 + j * 121;
    __nv_bfloat16* out = g_h1b + (size_t)bj * 3584;
    for (int cidx = threadIdx.x; cidx < 1792; cidx += blockDim.x) {
        float val = 0.f;
        if (cidx < 1771) {
            int l = 0;
            while (OFF1c[l + 1] <= cidx) l++;
            int k = 2 * l + 1;
            int local = cidx - OFF1c[l];
            int n = local / k;
            int m = local - n * k;
            val = cb[l * l + m] * pj[l * l + n];
        }
        __nv_bfloat16 hi = __float2bfloat16(val);
        __nv_bfloat16 lo = __float2bfloat16(val - __bfloat162float(hi));
        out[cidx] = hi;
        out[1792 + cidx] = lo;
    }
}

// --------------------------- split D1_to -----------------------------------
__global__ void k_splitB(const float* __restrict__ D1_to) {
    int n = blockIdx.x;
    const float* src = D1_to + (size_t)n * 1771;
    __nv_bfloat16* o = g_Db + (size_t)n * 3584;
    for (int k = threadIdx.x; k < 1792; k += blockDim.x) {
        float v = (k < 1771) ? src[k] : 0.f;
        __nv_bfloat16 hi = __float2bfloat16(v);
        __nv_bfloat16 lo = __float2bfloat16(v - __bfloat162float(hi));
        o[k] = hi;
        o[1792 + k] = lo;
    }
}

// --------------------------- stage F: psi2 ---------------------------------
__global__ void k_psi2(const float* __restrict__ Dk2, const float* __restrict__ w2) {
    int ij = blockIdx.x;
    int c = threadIdx.x;
    if (c < 286) {
        const float* w = w2 + ij * 168;
        float acc = 0.f;
        for (int n = 0; n < 168; n++) acc += Dk2[n * 286 + c] * w[n];
        g_psi2[ij * 286 + c] = acc * 0.07715167498104596f;
    }
}

// --------------------------- zero init -------------------------------------
__global__ void k_zero(float* __restrict__ out) {
    int i = blockIdx.x * blockDim.x + threadIdx.x;
    if (i < 640 * 286) g_h2[i] = 0.f;
    if (i < 1280) out[i] = 0.f;
}

// ======================= GEMM1: bf16x3 mma.sync ============================
// g_G[640,32000] = ACT*relu( h1[640,1771] @ D1_to[32000,1771]^T )
// CTA tile 128x128, BK=32, 8 warps (2m x 4n), warp tile 64x32.
// smem per stage: Ahi|Alo|Bhi|Blo, each 128 x 32 bf16 at pitch 40 halves.
#define PITCH 40
#define MATSZ (128 * PITCH)           // halves per matrix
#define STAGE (4 * MATSZ)             // halves per stage
static const int SMEM1_BYTES = 2 * STAGE * 2;  // 81920

__device__ __forceinline__ void load_stage1(uint32_t sb, int t, int m0, int n0,
                                            int stage, int kc) {
    uint32_t st = sb + (uint32_t)stage * (STAGE * 2);
    const __nv_bfloat16* srcs[4] = {
        g_h1b + (size_t)m0 * 3584 + kc * 32,           // Ahi
        g_h1b + (size_t)m0 * 3584 + 1792 + kc * 32,    // Alo
        g_Db  + (size_t)n0 * 3584 + kc * 32,           // Bhi
        g_Db  + (size_t)n0 * 3584 + 1792 + kc * 32,    // Blo
    };
#pragma unroll
    for (int mtx = 0; mtx < 4; mtx++) {
        uint32_t base = st + (uint32_t)mtx * (MATSZ * 2);
        const __nv_bfloat16* src = srcs[mtx];
#pragma unroll
        for (int i = 0; i < 2; i++) {
            int idx = t + 256 * i;      // 0..511
            int row = idx >> 2, ch = idx & 3;
            cp16(base + row * (PITCH * 2) + ch * 16,
                 src + (size_t)row * 3584 + ch * 8);
        }
    }
    CP_COMMIT();
}

__global__ void __launch_bounds__(256, 1) gemm1_mma() {
    extern __shared__ __align__(16) __nv_bfloat16 sm[];
    uint32_t sb = smem_u32(sm);
    const int t = threadIdx.x;
    const int warp = t >> 5, lane = t & 31;
    const int wm = warp & 1, wn = warp >> 1;       // 2 x 4 warp grid
    const int g = lane >> 2, tg = lane & 3;
    const int m0 = blockIdx.x * 128;               // m fastest: B-panel L2 reuse
    const int n0 = blockIdx.y * 128;

    float acc[4][4][4];
#pragma unroll
    for (int a = 0; a < 4; a++)
#pragma unroll
        for (int b = 0; b < 4; b++)
#pragma unroll
            for (int c = 0; c < 4; c++) acc[a][b][c] = 0.f;

    load_stage1(sb, t, m0, n0, 0, 0);
    load_stage1(sb, t, m0, n0, 1, 1);

    for (int kc = 0; kc < 56; kc++) {
        int buf = kc & 1;
        if (kc < 55) CP_WAIT1(); else CP_WAIT0();
        __syncthreads();

        const __nv_bfloat16* Ah = sm + buf * STAGE;
        const __nv_bfloat16* Al = Ah + MATSZ;
        const __nv_bfloat16* Bh = Al + MATSZ;
        const __nv_bfloat16* Bl = Bh + MATSZ;

#pragma unroll
        for (int s = 0; s < 2; s++) {
            const int k0 = s * 16 + tg * 2;
            uint32_t ah[4][4], al[4][4], bh[4][2], bl[4][2];
#pragma unroll
            for (int mt = 0; mt < 4; mt++) {
                int r = wm * 64 + mt * 16 + g;
                ah[mt][0] = *(const uint32_t*)&Ah[r * PITCH + k0];
                ah[mt][1] = *(const uint32_t*)&Ah[(r + 8) * PITCH + k0];
                ah[mt][2] = *(const uint32_t*)&Ah[r * PITCH + k0 + 8];
                ah[mt][3] = *(const uint32_t*)&Ah[(r + 8) * PITCH + k0 + 8];
                al[mt][0] = *(const uint32_t*)&Al[r * PITCH + k0];
                al[mt][1] = *(const uint32_t*)&Al[(r + 8) * PITCH + k0];
                al[mt][2] = *(const uint32_t*)&Al[r * PITCH + k0 + 8];
                al[mt][3] = *(const uint32_t*)&Al[(r + 8) * PITCH + k0 + 8];
            }
#pragma unroll
            for (int nt = 0; nt < 4; nt++) {
                int r = wn * 32 + nt * 8 + g;
                bh[nt][0] = *(const uint32_t*)&Bh[r * PITCH + k0];
                bh[nt][1] = *(const uint32_t*)&Bh[r * PITCH + k0 + 8];
                bl[nt][0] = *(const uint32_t*)&Bl[r * PITCH + k0];
                bl[nt][1] = *(const uint32_t*)&Bl[r * PITCH + k0 + 8];
            }
#pragma unroll
            for (int mt = 0; mt < 4; mt++)
#pragma unroll
                for (int nt = 0; nt < 4; nt++) {
                    mma16816(acc[mt][nt], ah[mt], bh[nt]);
                    mma16816(acc[mt][nt], ah[mt], bl[nt]);
                    mma16816(acc[mt][nt], al[mt], bh[nt]);
                }
        }
        __syncthreads();
        if (kc + 2 < 56) load_stage1(sb, t, m0, n0, buf, kc + 2);
    }

    // epilogue: relu * sqrt(2) -> g_G fp32
#pragma unroll
    for (int mt = 0; mt < 4; mt++) {
#pragma unroll
        for (int nt = 0; nt < 4; nt++) {
            int row = m0 + wm * 64 + mt * 16 + g;
            int col = n0 + wn * 32 + nt * 8 + tg * 2;
            float2 v0, v1;
            v0.x = fmaxf(acc[mt][nt][0], 0.f) * ACT_CST;
            v0.y = fmaxf(acc[mt][nt][1], 0.f) * ACT_CST;
            v1.x = fmaxf(acc[mt][nt][2], 0.f) * ACT_CST;
            v1.y = fmaxf(acc[mt][nt][3], 0.f) * ACT_CST;
            *(float2*)&g_G[(size_t)row * 32000 + col] = v0;
            *(float2*)&g_G[(size_t)(row + 8) * 32000 + col] = v1;
        }
    }
}

// --------------------------- tiled NT GEMM (fp32) --------------------------
// MODE 1: A=g_G,  C=g_h2, split-K atomic epilogue     (M=640,  N=286,  K=32000)
// MODE 2: A=g_h3, fused relu*ACT*wvec reduce -> Cout  (M=1280, N=6912, K=286)
template <int MODE>
__global__ void __launch_bounds__(256)
gemm_nt(const float* __restrict__ B, float* __restrict__ Cout,
        const float* __restrict__ wvec) {
    constexpr int N    = (MODE == 1) ? 286   : 6912;
    constexpr int K    = (MODE == 1) ? 32000 : 286;
    constexpr int KLEN = (MODE == 1) ? 800 : K;

    const float* A = (MODE == 1) ? g_G : g_h3;
    float* C       = (MODE == 1) ? g_h2 : Cout;

    __shared__ __align__(16) float As[16][132];
    __shared__ __align__(16) float Bs[16][68];

    const int t  = threadIdx.x;
    const int tx = t & 15;
    const int ty = t >> 4;
    const int m0 = blockIdx.y * 128;
    const int n0 = blockIdx.x * 64;
    const int kstart = (MODE == 1) ? (int)blockIdx.z * KLEN : 0;

    float acc[8][4];
#pragma unroll
    for (int i = 0; i < 8; i++)
#pragma unroll
        for (int j = 0; j < 4; j++) acc[i][j] = 0.f;

    const int kA = t & 15;
    const int rA = t >> 4;

    for (int kk = 0; kk < KLEN; kk += 16) {
        const bool kok = (kk + kA) < KLEN;
        const int kg = kstart + kk + kA;
#pragma unroll
        for (int i = 0; i < 8; i++) {
            int m = rA + 16 * i;
            As[kA][m] = kok ? A[(size_t)(m0 + m) * K + kg] : 0.f;
        }
#pragma unroll
        for (int i = 0; i < 4; i++) {
            int n = rA + 16 * i;
            Bs[kA][n] = (kok && (n0 + n) < N) ? B[(size_t)(n0 + n) * K + kg] : 0.f;
        }
        __syncthreads();
#pragma unroll
        for (int k = 0; k < 16; k++) {
            float4 a0 = *(const float4*)&As[k][ty * 8];
            float4 a1 = *(const float4*)&As[k][ty * 8 + 4];
            float4 bv = *(const float4*)&Bs[k][tx * 4];
            float av[8] = {a0.x, a0.y, a0.z, a0.w, a1.x, a1.y, a1.z, a1.w};
            float bb[4] = {bv.x, bv.y, bv.z, bv.w};
#pragma unroll
            for (int i = 0; i < 8; i++)
#pragma unroll
                for (int j = 0; j < 4; j++)
                    acc[i][j] = fmaf(av[i], bb[j], acc[i][j]);
        }
        __syncthreads();
    }

    if (MODE == 1) {
#pragma unroll
        for (int i = 0; i < 8; i++) {
            int row = m0 + ty * 8 + i;
#pragma unroll
            for (int j = 0; j < 4; j++) {
                int n = n0 + tx * 4 + j;
                if (n < N) atomicAdd(&C[row * N + n], acc[i][j]);
            }
        }
    } else {
#pragma unroll
        for (int i = 0; i < 8; i++) {
            int row = m0 + ty * 8 + i;
            float s = 0.f;
#pragma unroll
            for (int j = 0; j < 4; j++)
                s += fmaxf(acc[i][j], 0.f) * wvec[n0 + tx * 4 + j];
            atomicAdd(&C[row], s * ACT_CST);
        }
    }
}

// --------------------------- stage G: conv2 --------------------------------
__global__ void __launch_bounds__(320) k_conv2() {
    int bj = blockIdx.x;
    int b = bj / 40, j = bj - b * 40;
    __shared__ float h2s[20 * 286];
    __shared__ float ps[20 * 286];
    for (int idx = threadIdx.x; idx < 20 * 286; idx += blockDim.x) {
        int i = idx / 286, c = idx - i * 286;
        h2s[idx] = g_h2[(b * 20 + i) * 286 + c];
        ps[idx]  = g_psi2[(i * 40 + j) * 286 + c];
    }
    __syncthreads();
    int c = threadIdx.x;
    if (c < 286) {
        int l = 0;
        while (OFF2c[l + 1] <= c) l++;
        int k = 2 * l + 1;
        int local = c - OFF2c[l];
        int v = local / k;
        int m = local - v * k;
        int off = OFF2c[l];
        float acc = 0.f;
        for (int i = 0; i < 20; i++) {
            const float* hr = h2s + i * 286 + off;
            const float* pr = ps + i * 286 + off;
            for (int u = 0; u < k; u++)
                acc = fmaf(hr[u * k + m], pr[u * k + v], acc);
        }
        g_h3[bj * 286 + c] = acc * (1.0f / sqrtf(20.0f * (float)k));
    }
}

// --------------------------- launcher --------------------------------------
extern "C" void kernel_launch(void* const* d_in, const int* in_sizes, int n_in,
                              void* d_out, int out_size) {
    const float* x       = (const float*)d_in[0];
    const float* w1      = (const float*)d_in[1];
    const float* w2      = (const float*)d_in[2];
    const float* Yk1     = (const float*)d_in[3];
    const float* Dk2     = (const float*)d_in[4];
    const float* from_s2 = (const float*)d_in[5];
    const float* D1_to   = (const float*)d_in[6];
    const float* F1_from = (const float*)d_in[7];
    const float* D2_to   = (const float*)d_in[8];
    const float* F2_from = (const float*)d_in[9];
    float* out = (float*)d_out;
    (void)in_sizes; (void)n_in; (void)out_size;

    cudaFuncSetAttribute(gemm1_mma, cudaFuncAttributeMaxDynamicSharedMemorySize,
                         SMEM1_BYTES);

    k_zero<<<(640 * 286 + 255) / 256, 256>>>(out);
    k_xT<<<dim3(9, 32), dim3(32, 32)>>>(x);
    k_from_s2<<<dim3(121, 32), 128>>>(from_s2);
    k_psi1<<<20, 128>>>(Yk1, w1);
    k_h1b<<<640, 256>>>();
    k_splitB<<<32000, 256>>>(D1_to);
    // D: dominant GEMM on tensor cores (bf16x3 mma.sync); m fastest for B reuse
    gemm1_mma<<<dim3(5, 250), 256, SMEM1_BYTES>>>();
    k_psi2<<<800, 320>>>(Dk2, w2);
    // E: grid -> Fourier, split-K over K=32000
    gemm_nt<1><<<dim3(5, 5, 40), 256>>>(F1_from, nullptr, nullptr);
    k_conv2<<<1280, 320>>>();
    // H: final activation + projection, fused reduce into out
    gemm_nt<2><<<dim3(108, 10, 1), 256>>>(D2_to, out, F2_from);
}

// round 14
// speedup vs baseline: 2.7290x; 1.4822x over previous
#include <cuda_runtime.h>
#include <cuda_bf16.h>
#include <math.h>
#include <stdint.h>

// ---------------------------------------------------------------------------
// S2ConvNetModified pipeline. All three large GEMMs run on warp-level bf16
// mma.sync with a 3-term bf16 error split (hh + hl + lh) for fp32-class
// precision. (tcgen05 unavailable: harness compiles PTX at plain sm_103.)
//  A: c[32,121]      = xT @ from_s2^T                  (fp32 SIMT)
//  C: h1b            = outer products, bf16 hi/lo      Kp=1792
//  GEMM1: g_Gb[640,32000] = ACT*relu(h1 @ D1_to^T)     bf16x3 mma -> bf16 hi/lo
//  GEMM2: h2[640,286]     = G @ F1_from^T              bf16x3 mma, split-K
//  conv2: h3b[1280,286]   = block-diag Wigner conv     -> bf16 hi/lo, Kp=288
//  GEMM3: out[1280]       = sum_g F2_from*ACT*relu(h3 @ D2_to^T)  fused
// ---------------------------------------------------------------------------

#define ACT_CST 1.4142135623730951f

// ----- scratch (device globals; no runtime allocation allowed) -------------
__device__ float g_c[32 * 121];
__device__ float g_psi1[20 * 121];
__device__ float g_xT[32 * 9216];
__device__ __align__(16) __nv_bfloat16 g_h1b[640 * 3584];              // [hi|lo] Kp=1792
__device__ __align__(16) __nv_bfloat16 g_Db[(size_t)32000 * 3584];     // [hi|lo] D1_to
__device__ __align__(16) __nv_bfloat16 g_Gb[(size_t)640 * 64000];      // [hi|lo] Kp=32000
__device__ __align__(16) __nv_bfloat16 g_Fb[(size_t)384 * 64000];      // [hi|lo] F1_from (N pad 384)
__device__ __align__(16) __nv_bfloat16 g_D2b[(size_t)6912 * 576];      // [hi|lo] D2_to, Kp=288
__device__ __align__(16) __nv_bfloat16 g_h3b[1280 * 576];              // [hi|lo] Kp=288
__device__ float g_h2[640 * 286];
__device__ float g_psi2[800 * 286];

__constant__ int OFF1c[12] = {0, 1, 10, 35, 84, 165, 286, 455, 680, 969, 1330, 1771};
__constant__ int OFF2c[7]  = {0, 1, 10, 35, 84, 165, 286};

// ----------------------------- helpers -------------------------------------
__device__ __forceinline__ uint32_t smem_u32(const void* p) {
    uint32_t a;
    asm("{ .reg .u64 t; cvta.to.shared.u64 t, %1; cvt.u32.u64 %0, t; }"
        : "=r"(a) : "l"(p));
    return a;
}
__device__ __forceinline__ void cp16(uint32_t dst, const void* src) {
    asm volatile("cp.async.cg.shared.global [%0], [%1], 16;" :: "r"(dst), "l"(src));
}
#define CP_COMMIT() asm volatile("cp.async.commit_group;" ::: "memory")
#define CP_WAIT1()  asm volatile("cp.async.wait_group 1;" ::: "memory")
#define CP_WAIT0()  asm volatile("cp.async.wait_group 0;" ::: "memory")

__device__ __forceinline__ void mma16816(float* c, const uint32_t* a, const uint32_t* b) {
    asm volatile(
        "mma.sync.aligned.m16n8k16.row.col.f32.bf16.bf16.f32 "
        "{%0,%1,%2,%3},{%4,%5,%6,%7},{%8,%9},{%0,%1,%2,%3};"
        : "+f"(c[0]), "+f"(c[1]), "+f"(c[2]), "+f"(c[3])
        : "r"(a[0]), "r"(a[1]), "r"(a[2]), "r"(a[3]), "r"(b[0]), "r"(b[1]));
}
__device__ __forceinline__ void split_bf16(float v, __nv_bfloat16& hi, __nv_bfloat16& lo) {
    hi = __float2bfloat16(v);
    lo = __float2bfloat16(v - __bfloat162float(hi));
}

// --------------------------- x transpose -----------------------------------
__global__ void k_xT(const float* __restrict__ x) {
    __shared__ float t[32][33];
    int b = blockIdx.y;
    int ta = (blockIdx.x % 3) * 32, tb = (blockIdx.x / 3) * 32;
    t[threadIdx.y][threadIdx.x] = x[b * 9216 + (ta + threadIdx.y) * 96 + tb + threadIdx.x];
    __syncthreads();
    g_xT[b * 9216 + (tb + threadIdx.y) * 96 + ta + threadIdx.x] = t[threadIdx.x][threadIdx.y];
}

// --------------------------- stage A: from_s2 ------------------------------
__global__ void k_from_s2(const float* __restrict__ from_s2) {
    int m = blockIdx.x, b = blockIdx.y, t = threadIdx.x;
    const float* fr = from_s2 + (size_t)m * 9216;
    const float* xb = g_xT + (size_t)b * 9216;
    float acc = 0.f;
    for (int idx = t; idx < 9216; idx += 128) acc += fr[idx] * xb[idx];
    __shared__ float red[128];
    red[t] = acc;
    __syncthreads();
    for (int s = 64; s > 0; s >>= 1) {
        if (t < s) red[t] += red[t + s];
        __syncthreads();
    }
    if (t == 0) g_c[b * 121 + m] = red[0];
}

// --------------------------- stage B: psi1 ---------------------------------
__global__ void k_psi1(const float* __restrict__ Yk1, const float* __restrict__ w1) {
    int j = blockIdx.x, m = threadIdx.x;
    if (m < 121) {
        float acc = 0.f;
        for (int p = 0; p < 24; p++) acc += Yk1[p * 121 + m] * w1[j * 24 + p];
        g_psi1[j * 121 + m] = acc * 0.20412414523193154f;
    }
}

// --------------------------- stage C: h1 (bf16 split) ----------------------
__global__ void k_h1b() {
    int bj = blockIdx.x;
    int b = bj / 20, j = bj - b * 20;
    const float* cb = g_c + b * 121;
    const float* pj = g_psi1 + j * 121;
    __nv_bfloat16* out = g_h1b + (size_t)bj * 3584;
    for (int cidx = threadIdx.x; cidx < 1792; cidx += blockDim.x) {
        float val = 0.f;
        if (cidx < 1771) {
            int l = 0;
            while (OFF1c[l + 1] <= cidx) l++;
            int k = 2 * l + 1;
            int local = cidx - OFF1c[l];
            int n = local / k;
            int m = local - n * k;
            val = cb[l * l + m] * pj[l * l + n];
        }
        __nv_bfloat16 hi, lo;
        split_bf16(val, hi, lo);
        out[cidx] = hi;
        out[1792 + cidx] = lo;
    }
}

// --------------------------- weight splits ---------------------------------
__global__ void k_splitB(const float* __restrict__ D1_to) {
    int n = blockIdx.x;   // 0..31999
    const float* src = D1_to + (size_t)n * 1771;
    __nv_bfloat16* o = g_Db + (size_t)n * 3584;
    for (int k = threadIdx.x; k < 1792; k += blockDim.x) {
        float v = (k < 1771) ? src[k] : 0.f;
        __nv_bfloat16 hi, lo;
        split_bf16(v, hi, lo);
        o[k] = hi;
        o[1792 + k] = lo;
    }
}
__global__ void k_splitF(const float* __restrict__ F1_from) {
    int n = blockIdx.x;   // 0..383 (rows >=286 zero pad)
    __nv_bfloat16* o = g_Fb + (size_t)n * 64000;
    for (int k = threadIdx.x; k < 32000; k += blockDim.x) {
        float v = (n < 286) ? F1_from[(size_t)n * 32000 + k] : 0.f;
        __nv_bfloat16 hi, lo;
        split_bf16(v, hi, lo);
        o[k] = hi;
        o[32000 + k] = lo;
    }
}
__global__ void k_splitD2(const float* __restrict__ D2_to) {
    int n = blockIdx.x;   // 0..6911
    __nv_bfloat16* o = g_D2b + (size_t)n * 576;
    for (int k = threadIdx.x; k < 288; k += blockDim.x) {
        float v = (k < 286) ? D2_to[(size_t)n * 286 + k] : 0.f;
        __nv_bfloat16 hi, lo;
        split_bf16(v, hi, lo);
        o[k] = hi;
        o[288 + k] = lo;
    }
}

// --------------------------- stage F: psi2 ---------------------------------
__global__ void k_psi2(const float* __restrict__ Dk2, const float* __restrict__ w2) {
    int ij = blockIdx.x;
    int c = threadIdx.x;
    if (c < 286) {
        const float* w = w2 + ij * 168;
        float acc = 0.f;
        for (int n = 0; n < 168; n++) acc += Dk2[n * 286 + c] * w[n];
        g_psi2[ij * 286 + c] = acc * 0.07715167498104596f;
    }
}

// --------------------------- zero init -------------------------------------
__global__ void k_zero(float* __restrict__ out) {
    int i = blockIdx.x * blockDim.x + threadIdx.x;
    if (i < 640 * 286) g_h2[i] = 0.f;
    if (i < 1280) out[i] = 0.f;
}

// ======================= unified bf16x3 mma GEMM ===========================
// C = A @ B^T on [hi|lo]-split bf16 operands (per-row layout: hi at k,
// lo at Kp+k, row stride 2*Kp halves). CTA tile 128x128, BK=32,
// 8 warps (2m x 4n), warp tile 64x32.
// MODE 0 (GEMM1): A=g_h1b Kp=1792,  B=g_Db,  ep: relu*ACT -> g_Gb hi/lo
// MODE 1 (GEMM2): A=g_Gb  Kp=32000, B=g_Fb,  split-K=10, ep: atomicAdd g_h2
// MODE 2 (GEMM3): A=g_h3b Kp=288,   B=g_D2b, ep: relu*ACT*wvec reduce -> out
#define PITCH 40
#define MATSZ (128 * PITCH)
#define STAGE (4 * MATSZ)
static const int SMEM1_BYTES = 2 * STAGE * 2;  // 81920

__device__ __forceinline__ void ld_stage(uint32_t sb, int t,
                                         const __nv_bfloat16* A0,
                                         const __nv_bfloat16* B0,
                                         int Kp, int stage, int kc) {
    uint32_t st = sb + (uint32_t)stage * (STAGE * 2);
    const size_t stride = 2 * (size_t)Kp;
    const __nv_bfloat16* srcs[4] = {A0 + kc * 32, A0 + Kp + kc * 32,
                                    B0 + kc * 32, B0 + Kp + kc * 32};
#pragma unroll
    for (int mtx = 0; mtx < 4; mtx++) {
        uint32_t base = st + (uint32_t)mtx * (MATSZ * 2);
        const __nv_bfloat16* src = srcs[mtx];
#pragma unroll
        for (int i = 0; i < 2; i++) {
            int idx = t + 256 * i;
            int row = idx >> 2, ch = idx & 3;
            cp16(base + row * (PITCH * 2) + ch * 16, src + row * stride + ch * 8);
        }
    }
    CP_COMMIT();
}

template <int MODE>
__global__ void __launch_bounds__(256, 1) mma_gemm(const float* __restrict__ wvec,
                                                   float* __restrict__ outv) {
    constexpr int KP = (MODE == 0) ? 1792 : (MODE == 1) ? 32000 : 288;
    constexpr int CH = (MODE == 0) ? 56 : (MODE == 1) ? 100 : 9;

    extern __shared__ __align__(16) __nv_bfloat16 sm[];
    uint32_t sb = smem_u32(sm);
    const int t = threadIdx.x;
    const int warp = t >> 5, lane = t & 31;
    const int wm = warp & 1, wn = warp >> 1;
    const int g = lane >> 2, tg = lane & 3;
    const int m0 = blockIdx.x * 128;   // m fastest for B-panel L2 reuse
    const int n0 = blockIdx.y * 128;
    const int kbase = (MODE == 1) ? (int)blockIdx.z * 3200 : 0;

    const __nv_bfloat16* A0 =
        ((MODE == 0) ? g_h1b : (MODE == 1) ? g_Gb : g_h3b) +
        (size_t)m0 * (2 * KP) + kbase;
    const __nv_bfloat16* B0 =
        ((MODE == 0) ? g_Db : (MODE == 1) ? g_Fb : g_D2b) +
        (size_t)n0 * (2 * KP) + kbase;

    float acc[4][4][4];
#pragma unroll
    for (int a = 0; a < 4; a++)
#pragma unroll
        for (int b = 0; b < 4; b++)
#pragma unroll
            for (int c = 0; c < 4; c++) acc[a][b][c] = 0.f;

    ld_stage(sb, t, A0, B0, KP, 0, 0);
    ld_stage(sb, t, A0, B0, KP, 1, 1);

    for (int kc = 0; kc < CH; kc++) {
        int buf = kc & 1;
        if (kc < CH - 1) CP_WAIT1(); else CP_WAIT0();
        __syncthreads();

        const __nv_bfloat16* Ah = sm + buf * STAGE;
        const __nv_bfloat16* Al = Ah + MATSZ;
        const __nv_bfloat16* Bh = Al + MATSZ;
        const __nv_bfloat16* Bl = Bh + MATSZ;

#pragma unroll
        for (int s = 0; s < 2; s++) {
            const int k0 = s * 16 + tg * 2;
            uint32_t ah[4][4], al[4][4], bh[4][2], bl[4][2];
#pragma unroll
            for (int mt = 0; mt < 4; mt++) {
                int r = wm * 64 + mt * 16 + g;
                ah[mt][0] = *(const uint32_t*)&Ah[r * PITCH + k0];
                ah[mt][1] = *(const uint32_t*)&Ah[(r + 8) * PITCH + k0];
                ah[mt][2] = *(const uint32_t*)&Ah[r * PITCH + k0 + 8];
                ah[mt][3] = *(const uint32_t*)&Ah[(r + 8) * PITCH + k0 + 8];
                al[mt][0] = *(const uint32_t*)&Al[r * PITCH + k0];
                al[mt][1] = *(const uint32_t*)&Al[(r + 8) * PITCH + k0];
                al[mt][2] = *(const uint32_t*)&Al[r * PITCH + k0 + 8];
                al[mt][3] = *(const uint32_t*)&Al[(r + 8) * PITCH + k0 + 8];
            }
#pragma unroll
            for (int nt = 0; nt < 4; nt++) {
                int r = wn * 32 + nt * 8 + g;
                bh[nt][0] = *(const uint32_t*)&Bh[r * PITCH + k0];
                bh[nt][1] = *(const uint32_t*)&Bh[r * PITCH + k0 + 8];
                bl[nt][0] = *(const uint32_t*)&Bl[r * PITCH + k0];
                bl[nt][1] = *(const uint32_t*)&Bl[r * PITCH + k0 + 8];
            }
#pragma unroll
            for (int mt = 0; mt < 4; mt++)
#pragma unroll
                for (int nt = 0; nt < 4; nt++) {
                    mma16816(acc[mt][nt], ah[mt], bh[nt]);
                    mma16816(acc[mt][nt], ah[mt], bl[nt]);
                    mma16816(acc[mt][nt], al[mt], bh[nt]);
                }
        }
        __syncthreads();
        if (kc + 2 < CH) ld_stage(sb, t, A0, B0, KP, buf, kc + 2);
    }

    // ------------------------------ epilogues ------------------------------
    if (MODE == 0) {
        // relu * sqrt(2) -> g_Gb bf16 hi/lo (row stride 64000, lo at +32000)
#pragma unroll
        for (int mt = 0; mt < 4; mt++) {
#pragma unroll
            for (int nt = 0; nt < 4; nt++) {
                int row = m0 + wm * 64 + mt * 16 + g;
                int col = n0 + wn * 32 + nt * 8 + tg * 2;
#pragma unroll
                for (int half = 0; half < 2; half++) {
                    int r = row + 8 * half;
                    float vx = fmaxf(acc[mt][nt][2 * half], 0.f) * ACT_CST;
                    float vy = fmaxf(acc[mt][nt][2 * half + 1], 0.f) * ACT_CST;
                    __nv_bfloat162 h, l;
                    split_bf16(vx, h.x, l.x);
                    split_bf16(vy, h.y, l.y);
                    *(__nv_bfloat162*)&g_Gb[(size_t)r * 64000 + col] = h;
                    *(__nv_bfloat162*)&g_Gb[(size_t)r * 64000 + 32000 + col] = l;
                }
            }
        }
    } else if (MODE == 1) {
#pragma unroll
        for (int mt = 0; mt < 4; mt++) {
#pragma unroll
            for (int nt = 0; nt < 4; nt++) {
                int row = m0 + wm * 64 + mt * 16 + g;
                int col = n0 + wn * 32 + nt * 8 + tg * 2;
#pragma unroll
                for (int half = 0; half < 2; half++) {
                    int r = row + 8 * half;
                    if (col < 286) atomicAdd(&g_h2[r * 286 + col], acc[mt][nt][2 * half]);
                    if (col + 1 < 286) atomicAdd(&g_h2[r * 286 + col + 1], acc[mt][nt][2 * half + 1]);
                }
            }
        }
    } else {
        // relu * ACT * wvec[col], reduce over cols -> atomicAdd(out[row])
#pragma unroll
        for (int mt = 0; mt < 4; mt++) {
            float s0 = 0.f, s1 = 0.f;
#pragma unroll
            for (int nt = 0; nt < 4; nt++) {
                int col = n0 + wn * 32 + nt * 8 + tg * 2;
                float w0 = wvec[col], w1 = wvec[col + 1];
                s0 += fmaxf(acc[mt][nt][0], 0.f) * w0 + fmaxf(acc[mt][nt][1], 0.f) * w1;
                s1 += fmaxf(acc[mt][nt][2], 0.f) * w0 + fmaxf(acc[mt][nt][3], 0.f) * w1;
            }
            // lanes with equal g (tg = 0..3) hold same rows: butterfly over tg
            s0 += __shfl_xor_sync(0xFFFFFFFF, s0, 1);
            s0 += __shfl_xor_sync(0xFFFFFFFF, s0, 2);
            s1 += __shfl_xor_sync(0xFFFFFFFF, s1, 1);
            s1 += __shfl_xor_sync(0xFFFFFFFF, s1, 2);
            if (tg == 0) {
                int row = m0 + wm * 64 + mt * 16 + g;
                atomicAdd(&outv[row], s0 * ACT_CST);
                atomicAdd(&outv[row + 8], s1 * ACT_CST);
            }
        }
    }
}

// --------------------------- stage G: conv2 --------------------------------
// writes h3 as bf16 hi/lo with Kp=288 zero padding
__global__ void __launch_bounds__(320) k_conv2() {
    int bj = blockIdx.x;
    int b = bj / 40, j = bj - b * 40;
    __shared__ float h2s[20 * 286];
    __shared__ float ps[20 * 286];
    for (int idx = threadIdx.x; idx < 20 * 286; idx += blockDim.x) {
        int i = idx / 286, c = idx - i * 286;
        h2s[idx] = g_h2[(b * 20 + i) * 286 + c];
        ps[idx]  = g_psi2[(i * 40 + j) * 286 + c];
    }
    __syncthreads();
    int c = threadIdx.x;
    if (c < 288) {
        float val = 0.f;
        if (c < 286) {
            int l = 0;
            while (OFF2c[l + 1] <= c) l++;
            int k = 2 * l + 1;
            int local = c - OFF2c[l];
            int v = local / k;
            int m = local - v * k;
            int off = OFF2c[l];
            float acc = 0.f;
            for (int i = 0; i < 20; i++) {
                const float* hr = h2s + i * 286 + off;
                const float* pr = ps + i * 286 + off;
                for (int u = 0; u < k; u++)
                    acc = fmaf(hr[u * k + m], pr[u * k + v], acc);
            }
            val = acc * (1.0f / sqrtf(20.0f * (float)k));
        }
        __nv_bfloat16 hi, lo;
        split_bf16(val, hi, lo);
        g_h3b[bj * 576 + c] = hi;
        g_h3b[bj * 576 + 288 + c] = lo;
    }
}

// --------------------------- launcher --------------------------------------
extern "C" void kernel_launch(void* const* d_in, const int* in_sizes, int n_in,
                              void* d_out, int out_size) {
    const float* x       = (const float*)d_in[0];
    const float* w1      = (const float*)d_in[1];
    const float* w2      = (const float*)d_in[2];
    const float* Yk1     = (const float*)d_in[3];
    const float* Dk2     = (const float*)d_in[4];
    const float* from_s2 = (const float*)d_in[5];
    const float* D1_to   = (const float*)d_in[6];
    const float* F1_from = (const float*)d_in[7];
    const float* D2_to   = (const float*)d_in[8];
    const float* F2_from = (const float*)d_in[9];
    float* out = (float*)d_out;
    (void)in_sizes; (void)n_in; (void)out_size;

    cudaFuncSetAttribute(mma_gemm<0>, cudaFuncAttributeMaxDynamicSharedMemorySize, SMEM1_BYTES);
    cudaFuncSetAttribute(mma_gemm<1>, cudaFuncAttributeMaxDynamicSharedMemorySize, SMEM1_BYTES);
    cudaFuncSetAttribute(mma_gemm<2>, cudaFuncAttributeMaxDynamicSharedMemorySize, SMEM1_BYTES);

    k_zero<<<(640 * 286 + 255) / 256, 256>>>(out);
    k_xT<<<dim3(9, 32), dim3(32, 32)>>>(x);
    k_from_s2<<<dim3(121, 32), 128>>>(from_s2);
    k_psi1<<<20, 128>>>(Yk1, w1);
    k_h1b<<<640, 256>>>();
    k_splitB<<<32000, 256>>>(D1_to);
    k_splitF<<<384, 256>>>(F1_from);
    k_splitD2<<<6912, 128>>>(D2_to);
    // GEMM1: dominant grid transform, writes bf16 hi/lo for GEMM2
    mma_gemm<0><<<dim3(5, 250, 1), 256, SMEM1_BYTES>>>(nullptr, nullptr);
    k_psi2<<<800, 320>>>(Dk2, w2);
    // GEMM2: grid -> Fourier, split-K = 10
    mma_gemm<1><<<dim3(5, 3, 10), 256, SMEM1_BYTES>>>(nullptr, nullptr);
    // conv2 (emits bf16 hi/lo h3)
    k_conv2<<<1280, 320>>>();
    // GEMM3: final activation + projection, fused reduce into out
    mma_gemm<2><<<dim3(10, 54, 1), 256, SMEM1_BYTES>>>(F2_from, out);
}

// round 15
// speedup vs baseline: 3.0520x; 1.1184x over previous
#include <cuda_runtime.h>
#include <cuda_bf16.h>
#include <math.h>
#include <stdint.h>

// ---------------------------------------------------------------------------
// S2ConvNetModified pipeline. All three large GEMMs run on warp-level bf16
// mma.sync with a 3-term bf16 error split (hh + hl + lh) for fp32-class
// precision. (tcgen05 unavailable: harness compiles PTX at plain sm_103.)
// R15: GEMM retiled to 4 warps / 64x64 warp tiles (2 CTA/SM, half the
// smem-crossbar traffic per MAC).
// ---------------------------------------------------------------------------

#define ACT_CST 1.4142135623730951f

// ----- scratch (device globals; no runtime allocation allowed) -------------
__device__ float g_c[32 * 121];
__device__ float g_psi1[20 * 121];
__device__ float g_xT[32 * 9216];
__device__ __align__(16) __nv_bfloat16 g_h1b[640 * 3584];              // [hi|lo] Kp=1792
__device__ __align__(16) __nv_bfloat16 g_Db[(size_t)32000 * 3584];     // [hi|lo] D1_to
__device__ __align__(16) __nv_bfloat16 g_Gb[(size_t)640 * 64000];      // [hi|lo] Kp=32000
__device__ __align__(16) __nv_bfloat16 g_Fb[(size_t)384 * 64000];      // [hi|lo] F1_from
__device__ __align__(16) __nv_bfloat16 g_D2b[(size_t)6912 * 576];      // [hi|lo] D2_to Kp=288
__device__ __align__(16) __nv_bfloat16 g_h3b[1280 * 576];              // [hi|lo] Kp=288
__device__ float g_h2[640 * 286];
__device__ float g_psi2[800 * 286];

__constant__ int OFF1c[12] = {0, 1, 10, 35, 84, 165, 286, 455, 680, 969, 1330, 1771};
__constant__ int OFF2c[7]  = {0, 1, 10, 35, 84, 165, 286};

// ----------------------------- helpers -------------------------------------
__device__ __forceinline__ uint32_t smem_u32(const void* p) {
    uint32_t a;
    asm("{ .reg .u64 t; cvta.to.shared.u64 t, %1; cvt.u32.u64 %0, t; }"
        : "=r"(a) : "l"(p));
    return a;
}
__device__ __forceinline__ void cp16(uint32_t dst, const void* src) {
    asm volatile("cp.async.cg.shared.global [%0], [%1], 16;" :: "r"(dst), "l"(src));
}
#define CP_COMMIT() asm volatile("cp.async.commit_group;" ::: "memory")
#define CP_WAIT1()  asm volatile("cp.async.wait_group 1;" ::: "memory")
#define CP_WAIT0()  asm volatile("cp.async.wait_group 0;" ::: "memory")

__device__ __forceinline__ void mma16816(float* c, const uint32_t* a, const uint32_t* b) {
    asm volatile(
        "mma.sync.aligned.m16n8k16.row.col.f32.bf16.bf16.f32 "
        "{%0,%1,%2,%3},{%4,%5,%6,%7},{%8,%9},{%0,%1,%2,%3};"
        : "+f"(c[0]), "+f"(c[1]), "+f"(c[2]), "+f"(c[3])
        : "r"(a[0]), "r"(a[1]), "r"(a[2]), "r"(a[3]), "r"(b[0]), "r"(b[1]));
}
__device__ __forceinline__ void split_bf16(float v, __nv_bfloat16& hi, __nv_bfloat16& lo) {
    hi = __float2bfloat16(v);
    lo = __float2bfloat16(v - __bfloat162float(hi));
}

// --------------------------- x transpose -----------------------------------
__global__ void k_xT(const float* __restrict__ x) {
    __shared__ float t[32][33];
    int b = blockIdx.y;
    int ta = (blockIdx.x % 3) * 32, tb = (blockIdx.x / 3) * 32;
    t[threadIdx.y][threadIdx.x] = x[b * 9216 + (ta + threadIdx.y) * 96 + tb + threadIdx.x];
    __syncthreads();
    g_xT[b * 9216 + (tb + threadIdx.y) * 96 + ta + threadIdx.x] = t[threadIdx.x][threadIdx.y];
}

// --------------------------- stage A: from_s2 ------------------------------
__global__ void k_from_s2(const float* __restrict__ from_s2) {
    int m = blockIdx.x, b = blockIdx.y, t = threadIdx.x;
    const float* fr = from_s2 + (size_t)m * 9216;
    const float* xb = g_xT + (size_t)b * 9216;
    float acc = 0.f;
    for (int idx = t; idx < 9216; idx += 128) acc += fr[idx] * xb[idx];
    __shared__ float red[128];
    red[t] = acc;
    __syncthreads();
    for (int s = 64; s > 0; s >>= 1) {
        if (t < s) red[t] += red[t + s];
        __syncthreads();
    }
    if (t == 0) g_c[b * 121 + m] = red[0];
}

// --------------------------- stage B: psi1 ---------------------------------
__global__ void k_psi1(const float* __restrict__ Yk1, const float* __restrict__ w1) {
    int j = blockIdx.x, m = threadIdx.x;
    if (m < 121) {
        float acc = 0.f;
        for (int p = 0; p < 24; p++) acc += Yk1[p * 121 + m] * w1[j * 24 + p];
        g_psi1[j * 121 + m] = acc * 0.20412414523193154f;
    }
}

// --------------------------- stage C: h1 (bf16 split) ----------------------
__global__ void k_h1b() {
    int bj = blockIdx.x;
    int b = bj / 20, j = bj - b * 20;
    const float* cb = g_c + b * 121;
    const float* pj = g_psi1 + j * 121;
    __nv_bfloat16* out = g_h1b + (size_t)bj * 3584;
    for (int cidx = threadIdx.x; cidx < 1792; cidx += blockDim.x) {
        float val = 0.f;
        if (cidx < 1771) {
            int l = 0;
            while (OFF1c[l + 1] <= cidx) l++;
            int k = 2 * l + 1;
            int local = cidx - OFF1c[l];
            int n = local / k;
            int m = local - n * k;
            val = cb[l * l + m] * pj[l * l + n];
        }
        __nv_bfloat16 hi, lo;
        split_bf16(val, hi, lo);
        out[cidx] = hi;
        out[1792 + cidx] = lo;
    }
}

// --------------------------- weight splits ---------------------------------
__global__ void k_splitB(const float* __restrict__ D1_to) {
    int n = blockIdx.x;
    const float* src = D1_to + (size_t)n * 1771;
    __nv_bfloat16* o = g_Db + (size_t)n * 3584;
    for (int k = threadIdx.x; k < 1792; k += blockDim.x) {
        float v = (k < 1771) ? src[k] : 0.f;
        __nv_bfloat16 hi, lo;
        split_bf16(v, hi, lo);
        o[k] = hi;
        o[1792 + k] = lo;
    }
}
__global__ void k_splitF(const float* __restrict__ F1_from) {
    int n = blockIdx.x;
    __nv_bfloat16* o = g_Fb + (size_t)n * 64000;
    for (int k = threadIdx.x; k < 32000; k += blockDim.x) {
        float v = (n < 286) ? F1_from[(size_t)n * 32000 + k] : 0.f;
        __nv_bfloat16 hi, lo;
        split_bf16(v, hi, lo);
        o[k] = hi;
        o[32000 + k] = lo;
    }
}
__global__ void k_splitD2(const float* __restrict__ D2_to) {
    int n = blockIdx.x;
    __nv_bfloat16* o = g_D2b + (size_t)n * 576;
    for (int k = threadIdx.x; k < 288; k += blockDim.x) {
        float v = (k < 286) ? D2_to[(size_t)n * 286 + k] : 0.f;
        __nv_bfloat16 hi, lo;
        split_bf16(v, hi, lo);
        o[k] = hi;
        o[288 + k] = lo;
    }
}

// --------------------------- stage F: psi2 ---------------------------------
__global__ void k_psi2(const float* __restrict__ Dk2, const float* __restrict__ w2) {
    int ij = blockIdx.x;
    int c = threadIdx.x;
    if (c < 286) {
        const float* w = w2 + ij * 168;
        float acc = 0.f;
        for (int n = 0; n < 168; n++) acc += Dk2[n * 286 + c] * w[n];
        g_psi2[ij * 286 + c] = acc * 0.07715167498104596f;
    }
}

// --------------------------- zero init -------------------------------------
__global__ void k_zero(float* __restrict__ out) {
    int i = blockIdx.x * blockDim.x + threadIdx.x;
    if (i < 640 * 286) g_h2[i] = 0.f;
    if (i < 1280) out[i] = 0.f;
}

// ======================= unified bf16x3 mma GEMM ===========================
// C = A @ B^T on [hi|lo]-split bf16 operands. CTA tile 128x128, BK=32,
// 4 warps (2m x 2n), warp tile 64x64, 128 threads, 2 CTAs/SM.
// MODE 0 (GEMM1): A=g_h1b Kp=1792,  B=g_Db,  ep: relu*ACT -> g_Gb hi/lo
// MODE 1 (GEMM2): A=g_Gb  Kp=32000, B=g_Fb,  split-K=10, ep: atomicAdd g_h2
// MODE 2 (GEMM3): A=g_h3b Kp=288,   B=g_D2b, ep: relu*ACT*wvec reduce -> out
#define PITCH 40
#define MATSZ (128 * PITCH)
#define STAGE (4 * MATSZ)
static const int SMEM1_BYTES = 2 * STAGE * 2;  // 81920

__device__ __forceinline__ void ld_stage(uint32_t sb, int t,
                                         const __nv_bfloat16* A0,
                                         const __nv_bfloat16* B0,
                                         int Kp, int stage, int kc) {
    uint32_t st = sb + (uint32_t)stage * (STAGE * 2);
    const size_t stride = 2 * (size_t)Kp;
    const __nv_bfloat16* srcs[4] = {A0 + kc * 32, A0 + Kp + kc * 32,
                                    B0 + kc * 32, B0 + Kp + kc * 32};
#pragma unroll
    for (int mtx = 0; mtx < 4; mtx++) {
        uint32_t base = st + (uint32_t)mtx * (MATSZ * 2);
        const __nv_bfloat16* src = srcs[mtx];
#pragma unroll
        for (int i = 0; i < 4; i++) {            // 512 cp16 / 128 threads
            int idx = t + 128 * i;
            int row = idx >> 2, ch = idx & 3;
            cp16(base + row * (PITCH * 2) + ch * 16, src + row * stride + ch * 8);
        }
    }
    CP_COMMIT();
}

template <int MODE>
__global__ void __launch_bounds__(128, 2) mma_gemm(const float* __restrict__ wvec,
                                                   float* __restrict__ outv) {
    constexpr int KP = (MODE == 0) ? 1792 : (MODE == 1) ? 32000 : 288;
    constexpr int CH = (MODE == 0) ? 56 : (MODE == 1) ? 100 : 9;

    extern __shared__ __align__(16) __nv_bfloat16 sm[];
    uint32_t sb = smem_u32(sm);
    const int t = threadIdx.x;
    const int warp = t >> 5, lane = t & 31;
    const int wm = warp & 1, wn = warp >> 1;       // 2 x 2 warp grid
    const int g = lane >> 2, tg = lane & 3;
    const int m0 = blockIdx.x * 128;               // m fastest: B-panel L2 reuse
    const int n0 = blockIdx.y * 128;
    const int kbase = (MODE == 1) ? (int)blockIdx.z * 3200 : 0;

    const __nv_bfloat16* A0 =
        ((MODE == 0) ? g_h1b : (MODE == 1) ? g_Gb : g_h3b) +
        (size_t)m0 * (2 * KP) + kbase;
    const __nv_bfloat16* B0 =
        ((MODE == 0) ? g_Db : (MODE == 1) ? g_Fb : g_D2b) +
        (size_t)n0 * (2 * KP) + kbase;

    float acc[4][8][4];
#pragma unroll
    for (int a = 0; a < 4; a++)
#pragma unroll
        for (int b = 0; b < 8; b++)
#pragma unroll
            for (int c = 0; c < 4; c++) acc[a][b][c] = 0.f;

    ld_stage(sb, t, A0, B0, KP, 0, 0);
    ld_stage(sb, t, A0, B0, KP, 1, 1);

    for (int kc = 0; kc < CH; kc++) {
        int buf = kc & 1;
        if (kc < CH - 1) CP_WAIT1(); else CP_WAIT0();
        __syncthreads();

        const __nv_bfloat16* Ah = sm + buf * STAGE;
        const __nv_bfloat16* Al = Ah + MATSZ;
        const __nv_bfloat16* Bh = Al + MATSZ;
        const __nv_bfloat16* Bl = Bh + MATSZ;

#pragma unroll
        for (int s = 0; s < 2; s++) {
            const int k0 = s * 16 + tg * 2;
            uint32_t ah[4][4], al[4][4];
#pragma unroll
            for (int mt = 0; mt < 4; mt++) {
                int r = wm * 64 + mt * 16 + g;
                ah[mt][0] = *(const uint32_t*)&Ah[r * PITCH + k0];
                ah[mt][1] = *(const uint32_t*)&Ah[(r + 8) * PITCH + k0];
                ah[mt][2] = *(const uint32_t*)&Ah[r * PITCH + k0 + 8];
                ah[mt][3] = *(const uint32_t*)&Ah[(r + 8) * PITCH + k0 + 8];
                al[mt][0] = *(const uint32_t*)&Al[r * PITCH + k0];
                al[mt][1] = *(const uint32_t*)&Al[(r + 8) * PITCH + k0];
                al[mt][2] = *(const uint32_t*)&Al[r * PITCH + k0 + 8];
                al[mt][3] = *(const uint32_t*)&Al[(r + 8) * PITCH + k0 + 8];
            }
#pragma unroll
            for (int nt = 0; nt < 8; nt++) {
                int r = wn * 64 + nt * 8 + g;
                uint32_t bh[2], bl[2];
                bh[0] = *(const uint32_t*)&Bh[r * PITCH + k0];
                bh[1] = *(const uint32_t*)&Bh[r * PITCH + k0 + 8];
                bl[0] = *(const uint32_t*)&Bl[r * PITCH + k0];
                bl[1] = *(const uint32_t*)&Bl[r * PITCH + k0 + 8];
#pragma unroll
                for (int mt = 0; mt < 4; mt++) {
                    mma16816(acc[mt][nt], ah[mt], bh);
                    mma16816(acc[mt][nt], ah[mt], bl);
                    mma16816(acc[mt][nt], al[mt], bh);
                }
            }
        }
        __syncthreads();
        if (kc + 2 < CH) ld_stage(sb, t, A0, B0, KP, buf, kc + 2);
    }

    // ------------------------------ epilogues ------------------------------
    if (MODE == 0) {
#pragma unroll
        for (int mt = 0; mt < 4; mt++) {
#pragma unroll
            for (int nt = 0; nt < 8; nt++) {
                int row = m0 + wm * 64 + mt * 16 + g;
                int col = n0 + wn * 64 + nt * 8 + tg * 2;
#pragma unroll
                for (int half = 0; half < 2; half++) {
                    int r = row + 8 * half;
                    float vx = fmaxf(acc[mt][nt][2 * half], 0.f) * ACT_CST;
                    float vy = fmaxf(acc[mt][nt][2 * half + 1], 0.f) * ACT_CST;
                    __nv_bfloat162 h, l;
                    split_bf16(vx, h.x, l.x);
                    split_bf16(vy, h.y, l.y);
                    *(__nv_bfloat162*)&g_Gb[(size_t)r * 64000 + col] = h;
                    *(__nv_bfloat162*)&g_Gb[(size_t)r * 64000 + 32000 + col] = l;
                }
            }
        }
    } else if (MODE == 1) {
#pragma unroll
        for (int mt = 0; mt < 4; mt++) {
#pragma unroll
            for (int nt = 0; nt < 8; nt++) {
                int row = m0 + wm * 64 + mt * 16 + g;
                int col = n0 + wn * 64 + nt * 8 + tg * 2;
#pragma unroll
                for (int half = 0; half < 2; half++) {
                    int r = row + 8 * half;
                    if (col < 286) atomicAdd(&g_h2[r * 286 + col], acc[mt][nt][2 * half]);
                    if (col + 1 < 286) atomicAdd(&g_h2[r * 286 + col + 1], acc[mt][nt][2 * half + 1]);
                }
            }
        }
    } else {
#pragma unroll
        for (int mt = 0; mt < 4; mt++) {
            float s0 = 0.f, s1 = 0.f;
#pragma unroll
            for (int nt = 0; nt < 8; nt++) {
                int col = n0 + wn * 64 + nt * 8 + tg * 2;
                float w0 = wvec[col], w1 = wvec[col + 1];
                s0 += fmaxf(acc[mt][nt][0], 0.f) * w0 + fmaxf(acc[mt][nt][1], 0.f) * w1;
                s1 += fmaxf(acc[mt][nt][2], 0.f) * w0 + fmaxf(acc[mt][nt][3], 0.f) * w1;
            }
            s0 += __shfl_xor_sync(0xFFFFFFFF, s0, 1);
            s0 += __shfl_xor_sync(0xFFFFFFFF, s0, 2);
            s1 += __shfl_xor_sync(0xFFFFFFFF, s1, 1);
            s1 += __shfl_xor_sync(0xFFFFFFFF, s1, 2);
            if (tg == 0) {
                int row = m0 + wm * 64 + mt * 16 + g;
                atomicAdd(&outv[row], s0 * ACT_CST);
                atomicAdd(&outv[row + 8], s1 * ACT_CST);
            }
        }
    }
}

// --------------------------- stage G: conv2 --------------------------------
__global__ void __launch_bounds__(320) k_conv2() {
    int bj = blockIdx.x;
    int b = bj / 40, j = bj - b * 40;
    __shared__ float h2s[20 * 286];
    __shared__ float ps[20 * 286];
    for (int idx = threadIdx.x; idx < 20 * 286; idx += blockDim.x) {
        int i = idx / 286, c = idx - i * 286;
        h2s[idx] = g_h2[(b * 20 + i) * 286 + c];
        ps[idx]  = g_psi2[(i * 40 + j) * 286 + c];
    }
    __syncthreads();
    int c = threadIdx.x;
    if (c < 288) {
        float val = 0.f;
        if (c < 286) {
            int l = 0;
            while (OFF2c[l + 1] <= c) l++;
            int k = 2 * l + 1;
            int local = c - OFF2c[l];
            int v = local / k;
            int m = local - v * k;
            int off = OFF2c[l];
            float acc = 0.f;
            for (int i = 0; i < 20; i++) {
                const float* hr = h2s + i * 286 + off;
                const float* pr = ps + i * 286 + off;
                for (int u = 0; u < k; u++)
                    acc = fmaf(hr[u * k + m], pr[u * k + v], acc);
            }
            val = acc * (1.0f / sqrtf(20.0f * (float)k));
        }
        __nv_bfloat16 hi, lo;
        split_bf16(val, hi, lo);
        g_h3b[bj * 576 + c] = hi;
        g_h3b[bj * 576 + 288 + c] = lo;
    }
}

// --------------------------- launcher --------------------------------------
extern "C" void kernel_launch(void* const* d_in, const int* in_sizes, int n_in,
                              void* d_out, int out_size) {
    const float* x       = (const float*)d_in[0];
    const float* w1      = (const float*)d_in[1];
    const float* w2      = (const float*)d_in[2];
    const float* Yk1     = (const float*)d_in[3];
    const float* Dk2     = (const float*)d_in[4];
    const float* from_s2 = (const float*)d_in[5];
    const float* D1_to   = (const float*)d_in[6];
    const float* F1_from = (const float*)d_in[7];
    const float* D2_to   = (const float*)d_in[8];
    const float* F2_from = (const float*)d_in[9];
    float* out = (float*)d_out;
    (void)in_sizes; (void)n_in; (void)out_size;

    cudaFuncSetAttribute(mma_gemm<0>, cudaFuncAttributeMaxDynamicSharedMemorySize, SMEM1_BYTES);
    cudaFuncSetAttribute(mma_gemm<1>, cudaFuncAttributeMaxDynamicSharedMemorySize, SMEM1_BYTES);
    cudaFuncSetAttribute(mma_gemm<2>, cudaFuncAttributeMaxDynamicSharedMemorySize, SMEM1_BYTES);

    k_zero<<<(640 * 286 + 255) / 256, 256>>>(out);
    k_xT<<<dim3(9, 32), dim3(32, 32)>>>(x);
    k_from_s2<<<dim3(121, 32), 128>>>(from_s2);
    k_psi1<<<20, 128>>>(Yk1, w1);
    k_h1b<<<640, 256>>>();
    k_splitB<<<32000, 256>>>(D1_to);
    k_splitF<<<384, 256>>>(F1_from);
    k_splitD2<<<6912, 128>>>(D2_to);
    // GEMM1: dominant grid transform, writes bf16 hi/lo for GEMM2
    mma_gemm<0><<<dim3(5, 250, 1), 128, SMEM1_BYTES>>>(nullptr, nullptr);
    k_psi2<<<800, 320>>>(Dk2, w2);
    // GEMM2: grid -> Fourier, split-K = 10
    mma_gemm<1><<<dim3(5, 3, 10), 128, SMEM1_BYTES>>>(nullptr, nullptr);
    // conv2 (emits bf16 hi/lo h3)
    k_conv2<<<1280, 320>>>();
    // GEMM3: final activation + projection, fused reduce into out
    mma_gemm<2><<<dim3(10, 54, 1), 128, SMEM1_BYTES>>>(F2_from, out);
}